// round 3
// baseline (speedup 1.0000x reference)
#include <cuda_runtime.h>
#include <cstdint>

// ============================================================================
// 2-layer SimpleRNN, persistent-kernel fp32 baseline (f32x2 FMA).
//   h0[t] = tanh([x_t | h0[t-1]] @ [W0x; W0h] + b0)
//   h1[t] = tanh([h0[t] | h1[t-1]] @ [W1x; W1h] + b1)
//   out   = sigmoid(h1[T-1] @ Wout + bout)
// One kernel, 128 CTAs x 256 threads, software grid barrier between the
// 160 dependent GEMM phases. Each phase: 64x64 output tile per CTA, K=1024.
// Token dtype (int32 vs int64) is auto-detected at runtime.
// ============================================================================

#define NCTA   128
#define NTHR   256
#define BM     64
#define BN     64
#define BK     16
#define AP     (BM + 2)     // 66: pad to kill LDS/STS bank conflicts
#define BD     (2 * BN)     // 128: B stored duplicated (b,b) for f32x2 FMA
#define B_SZ   1024
#define T_SZ   80
#define U_SZ   512
#define KTOT   1024
#define NCHUNK (KTOT / BK)  // 64

// Persistent scratch (static __device__ — no allocations allowed)
__device__ float g_h0[2][B_SZ * U_SZ];
__device__ float g_h1[2][B_SZ * U_SZ];
__device__ unsigned g_arrive = 0;
__device__ unsigned g_gen    = 0;   // monotonic across graph replays

// packed fp32x2 FMA: acc.{lo,hi} += a.{lo,hi} * b.{lo,hi}
__device__ __forceinline__ void fma2(unsigned long long &acc,
                                     unsigned long long a,
                                     unsigned long long b) {
    asm("fma.rn.f32x2 %0, %1, %2, %0;" : "+l"(acc) : "l"(a), "l"(b));
}

__device__ __forceinline__ float2 u2f(unsigned long long u) {
    float2 f;
    asm("mov.b64 {%0, %1}, %2;" : "=f"(f.x), "=f"(f.y) : "l"(u));
    return f;
}

// Sense-free generation barrier. barBase is the g_gen snapshot taken at kernel
// entry (valid in thread 0 only), n is the barrier ordinal within this launch.
__device__ __forceinline__ void grid_barrier(unsigned barBase, unsigned n) {
    __syncthreads();
    if (threadIdx.x == 0) {
        __threadfence();                       // release our CTA's stores
        unsigned rank = atomicAdd(&g_arrive, 1);
        if (rank == NCTA - 1) {
            g_arrive = 0;
            __threadfence();
            atomicAdd(&g_gen, 1);
        } else {
            unsigned target = barBase + n;
            while ((int)(*(volatile unsigned *)&g_gen - target) < 0) { }
            __threadfence();                   // acquire
        }
    }
    __syncthreads();
}

struct Smem {
    float As[2][BK][AP];   // k-major A tile (transposed on store)
    float Bs[2][BK][BD];   // duplicated B tile: Bs[k][2c]=Bs[k][2c+1]=W[k][c]
    int   toks[BM];
};

// One GEMM phase: dst[row0:+64, col0:+64] =
//   tanh( A[rows, 0:512]@Wx + A[rows, 512:1024]@Wh + bias )
// where A first half = emb-gather (use_emb) or xsrc rows, second half = hold.
__device__ __forceinline__ void do_phase(
    Smem *sm, bool use_emb,
    const float *__restrict__ xsrc,          // emb (use_emb) or h0_new
    const int *__restrict__ tok32, int tokStride, int t,
    const float *__restrict__ hold,          // recurrent h (previous step)
    const float *__restrict__ Wx, const float *__restrict__ Wh,
    const float *__restrict__ bias,
    float *__restrict__ dst, int row0, int col0)
{
    const int tid  = threadIdx.x;
    const int tx   = tid & 15;        // 16 col-groups of 4
    const int ty   = tid >> 4;        // 16 row-groups of 4
    const int arow = tid >> 2;        // A loader: row 0..63
    const int aq   = tid & 3;         // A loader: k-quad 0..3
    const int bkr  = tid >> 4;        // B loader: k-row 0..15
    const int bq   = tid & 15;        // B loader: col-quad 0..15

    if (use_emb && tid < BM) {
        size_t idx = (size_t)(row0 + tid) * T_SZ + t;
        sm->toks[tid] = tok32[idx * tokStride];   // stride 2 if int64 layout
    }
    __syncthreads();

    unsigned long long acc[2][4];
#pragma unroll
    for (int i = 0; i < 2; i++)
#pragma unroll
        for (int j = 0; j < 4; j++) acc[i][j] = 0ull;

    float4 av, bv;

    auto ldA = [&](int kc, float4 &v) {
        int kg = kc * BK + 4 * aq;
        if (kg < U_SZ) {
            if (use_emb) {
                const float *p = xsrc + (size_t)sm->toks[arow] * U_SZ + kg;
                v = __ldg(reinterpret_cast<const float4 *>(p));
            } else {
                // freshly produced h0 — must bypass L1 (written by other CTAs)
                const float *p = xsrc + (size_t)(row0 + arow) * U_SZ + kg;
                v = __ldcg(reinterpret_cast<const float4 *>(p));
            }
        } else {
            const float *p = hold + (size_t)(row0 + arow) * U_SZ + (kg - U_SZ);
            v = __ldcg(reinterpret_cast<const float4 *>(p));
        }
    };
    auto ldB = [&](int kc, float4 &v) {
        int kg = kc * BK + bkr;
        const float *W = (kg < U_SZ) ? (Wx + (size_t)kg * U_SZ)
                                     : (Wh + (size_t)(kg - U_SZ) * U_SZ);
        v = __ldg(reinterpret_cast<const float4 *>(W + col0 + 4 * bq));
    };
    auto stA = [&](int buf, const float4 &v) {
        int kb = 4 * aq;               // transpose: As[k][row]
        sm->As[buf][kb + 0][arow] = v.x;
        sm->As[buf][kb + 1][arow] = v.y;
        sm->As[buf][kb + 2][arow] = v.z;
        sm->As[buf][kb + 3][arow] = v.w;
    };
    auto stB = [&](int buf, const float4 &v) {
        float *d = &sm->Bs[buf][bkr][8 * bq];   // duplicate each value
        *reinterpret_cast<float4 *>(d)     = make_float4(v.x, v.x, v.y, v.y);
        *reinterpret_cast<float4 *>(d + 4) = make_float4(v.z, v.z, v.w, v.w);
    };

    ldA(0, av); ldB(0, bv);
    stA(0, av); stB(0, bv);
    __syncthreads();

#pragma unroll 1
    for (int kc = 0; kc < NCHUNK; kc++) {
        int cur = kc & 1;
        if (kc + 1 < NCHUNK) { ldA(kc + 1, av); ldB(kc + 1, bv); }
        const float *Asb = &sm->As[cur][0][0];
        const float *Bsb = &sm->Bs[cur][0][0];
#pragma unroll
        for (int kk = 0; kk < BK; kk++) {
            // a: two row-pairs (vector LDS, broadcast across col-groups)
            unsigned long long a01 =
                *reinterpret_cast<const unsigned long long *>(Asb + kk * AP + 4 * ty);
            unsigned long long a23 =
                *reinterpret_cast<const unsigned long long *>(Asb + kk * AP + 4 * ty + 2);
            // b: four duplicated pairs (b,b) — no per-k register packing needed
            ulonglong2 bL = *reinterpret_cast<const ulonglong2 *>(Bsb + kk * BD + 8 * tx);
            ulonglong2 bH = *reinterpret_cast<const ulonglong2 *>(Bsb + kk * BD + 8 * tx + 4);
            fma2(acc[0][0], a01, bL.x); fma2(acc[0][1], a01, bL.y);
            fma2(acc[0][2], a01, bH.x); fma2(acc[0][3], a01, bH.y);
            fma2(acc[1][0], a23, bL.x); fma2(acc[1][1], a23, bL.y);
            fma2(acc[1][2], a23, bH.x); fma2(acc[1][3], a23, bH.y);
        }
        if (kc + 1 < NCHUNK) {
            stA(cur ^ 1, av); stB(cur ^ 1, bv);
            __syncthreads();
        }
    }

    // epilogue: bias + tanh, coalesced float4 stores
    float ob[4];
#pragma unroll
    for (int c = 0; c < 4; c++) ob[c] = __ldg(bias + col0 + 4 * tx + c);

    float o[4][4];
#pragma unroll
    for (int c = 0; c < 4; c++) {
        float2 p0 = u2f(acc[0][c]);
        float2 p1 = u2f(acc[1][c]);
        o[0][c] = p0.x; o[1][c] = p0.y; o[2][c] = p1.x; o[3][c] = p1.y;
    }
#pragma unroll
    for (int r = 0; r < 4; r++) {
        float4 v = make_float4(tanhf(o[r][0] + ob[0]), tanhf(o[r][1] + ob[1]),
                               tanhf(o[r][2] + ob[2]), tanhf(o[r][3] + ob[3]));
        *reinterpret_cast<float4 *>(
            dst + (size_t)(row0 + 4 * ty + r) * U_SZ + col0 + 4 * tx) = v;
    }
}

extern "C" __global__ void __launch_bounds__(NTHR, 1)
rnn_kernel(const int *__restrict__ tok32,
           const float *__restrict__ emb,
           const float *__restrict__ W0x, const float *__restrict__ W0h,
           const float *__restrict__ b0,
           const float *__restrict__ W1x, const float *__restrict__ W1h,
           const float *__restrict__ b1,
           const float *__restrict__ Wout, const float *__restrict__ bout,
           float *__restrict__ out)
{
    __shared__ Smem sm;
    const int tid  = threadIdx.x;
    const int cta  = blockIdx.x;
    const int row0 = (cta >> 3) * BM;   // 16 row tiles
    const int col0 = (cta & 7)  * BN;   //  8 col tiles

    unsigned barBase = 0;
    if (tid == 0) barBase = *(volatile unsigned *)&g_gen;  // replay-safe snapshot
    unsigned nb = 0;

    // --- token dtype auto-detect (uniform across all threads/CTAs) ---
    // int64 layout: positive tokens < 50000 => every odd 32-bit word == 0.
    // int32 layout: odd words are tokens; P(all 32 sampled == 0) ~ 0.
    __shared__ int s_tokStride;
    if (tid == 0) {
        bool all_hi_zero = true;
#pragma unroll 1
        for (int i = 0; i < 32; i++)
            if (__ldg(tok32 + 2 * i + 1) != 0) { all_hi_zero = false; break; }
        s_tokStride = all_hi_zero ? 2 : 1;
    }
    __syncthreads();
    const int tokStride = s_tokStride;

    // zero-init the t=0 state buffers (re-done every launch: deterministic)
    for (int i = cta * NTHR + tid; i < B_SZ * U_SZ; i += NCTA * NTHR) {
        g_h0[0][i] = 0.f;
        g_h1[0][i] = 0.f;
    }
    grid_barrier(barBase, ++nb);

    for (int t = 0; t < T_SZ; t++) {
        int po = t & 1, pn = po ^ 1;
        // cell 0: [x_t | h0_old] @ [W0x; W0h]
        do_phase(&sm, true,  emb,      tok32, tokStride, t, g_h0[po],
                 W0x, W0h, b0, g_h0[pn], row0, col0);
        grid_barrier(barBase, ++nb);
        // cell 1: [h0_new | h1_old] @ [W1x; W1h]
        do_phase(&sm, false, g_h0[pn], nullptr, 1, 0, g_h1[po],
                 W1x, W1h, b1, g_h1[pn], row0, col0);
        grid_barrier(barBase, ++nb);
    }

    // final: out[b] = sigmoid(h1_last[b] . Wout + bout)
    const float *h1f = g_h1[((T_SZ - 1) & 1) ^ 1];
    int w = tid >> 5, lane = tid & 31;
    int b = cta * 8 + w;                 // 128 CTAs * 8 warps = 1024 rows
    float s = 0.f;
#pragma unroll
    for (int j = 0; j < 16; j++) {
        int k = lane + 32 * j;
        s += __ldcg(h1f + (size_t)b * U_SZ + k) * __ldg(Wout + k);
    }
#pragma unroll
    for (int off = 16; off; off >>= 1) s += __shfl_down_sync(0xffffffffu, s, off);
    if (lane == 0) {
        float z = s + __ldg(bout);
        out[b] = 1.f / (1.f + expf(-z));
    }
}

extern "C" void kernel_launch(void *const *d_in, const int *in_sizes, int n_in,
                              void *d_out, int out_size)
{
    const int   *inputs = (const int *)d_in[0];
    const float *emb  = (const float *)d_in[1];
    const float *W0x  = (const float *)d_in[2];
    const float *W0h  = (const float *)d_in[3];
    const float *b0   = (const float *)d_in[4];
    const float *W1x  = (const float *)d_in[5];
    const float *W1h  = (const float *)d_in[6];
    const float *b1   = (const float *)d_in[7];
    const float *Wout = (const float *)d_in[8];
    const float *bout = (const float *)d_in[9];
    rnn_kernel<<<NCTA, NTHR>>>(inputs, emb, W0x, W0h, b0, W1x, W1h, b1,
                               Wout, bout, (float *)d_out);
}

// round 11
// speedup vs baseline: 5.3725x; 5.3725x over previous
#include <cuda_runtime.h>
#include <cuda_bf16.h>
#include <cstdint>

// ============================================================================
// 2-layer SimpleRNN via warp-level mma.sync (bf16 hi/lo 3-pass, f32 accum).
// Persistent kernel: 128 CTAs x 256 thr, grid barrier between 160 phases.
// Per phase each CTA computes a 64(batch) x 64(unit) tile, K=1024 in
// 16 K-chunks of 64, smem-staged, ldmatrix + mma.m16n8k16 (base sm_103 PTX).
// h state kept fp32 in global; bf16 split happens at staging time.
// ============================================================================

#define NCTA  128
#define NTHR  256
#define B_SZ  1024
#define T_SZ  80
#define U_SZ  512
#define KTOT  1024

// smem: row stride 144 B = 64 bf16 data + 16 B pad (conflict-free LDSM/STS)
// regions: 64 rows x 144 B = 9216 B each
#define A_HI  0
#define A_LO  9216
#define B_HI  18432
#define B_LO  27648
#define TOKS  36864
#define SM_BYTES 37120

// ---- global scratch ----
__device__ __nv_bfloat16 g_Bhi[2][U_SZ * KTOT];  // [cell][n*1024+k] = Wcat[k][n]
__device__ __nv_bfloat16 g_Blo[2][U_SZ * KTOT];
__device__ float g_h0[2][B_SZ * U_SZ];
__device__ float g_h1[2][B_SZ * U_SZ];
__device__ unsigned g_arrive = 0, g_gen = 0;

__device__ __forceinline__ uint32_t smem_u32(const void *p) {
    uint32_t a;
    asm("{ .reg .u64 t; cvta.to.shared.u64 t, %1; cvt.u32.u64 %0, t; }"
        : "=r"(a) : "l"(p));
    return a;
}
#define LDSM4(r, a) \
    asm volatile("ldmatrix.sync.aligned.m8n8.x4.shared.b16 {%0,%1,%2,%3}, [%4];" \
        : "=r"((r)[0]), "=r"((r)[1]), "=r"((r)[2]), "=r"((r)[3]) : "r"(a))

__device__ __forceinline__ void mma_bf16(float *d, const uint32_t *a,
                                         uint32_t b0, uint32_t b1) {
    asm volatile(
        "mma.sync.aligned.m16n8k16.row.col.f32.bf16.bf16.f32 "
        "{%0,%1,%2,%3}, {%4,%5,%6,%7}, {%8,%9}, {%0,%1,%2,%3};"
        : "+f"(d[0]), "+f"(d[1]), "+f"(d[2]), "+f"(d[3])
        : "r"(a[0]), "r"(a[1]), "r"(a[2]), "r"(a[3]), "r"(b0), "r"(b1));
}

// ---- grid barrier (proven R3) ----
__device__ __forceinline__ void grid_barrier(unsigned barBase, unsigned n) {
    __syncthreads();
    if (threadIdx.x == 0) {
        __threadfence();
        unsigned rank = atomicAdd(&g_arrive, 1);
        if (rank == NCTA - 1) {
            g_arrive = 0;
            __threadfence();
            atomicAdd(&g_gen, 1);
        } else {
            unsigned target = barBase + n;
            while ((int)(*(volatile unsigned *)&g_gen - target) < 0) { }
            __threadfence();
        }
    }
    __syncthreads();
}

__device__ __forceinline__ void split4(float4 v, uint2 &hi, uint2 &lo) {
    __nv_bfloat16 hx = __float2bfloat16(v.x), hy = __float2bfloat16(v.y);
    __nv_bfloat16 hz = __float2bfloat16(v.z), hw = __float2bfloat16(v.w);
    union { uint2 u; __nv_bfloat162 b[2]; } H, L;
    H.b[0] = __halves2bfloat162(hx, hy);
    H.b[1] = __halves2bfloat162(hz, hw);
    L.b[0] = __halves2bfloat162(__float2bfloat16(v.x - __bfloat162float(hx)),
                                __float2bfloat16(v.y - __bfloat162float(hy)));
    L.b[1] = __halves2bfloat162(__float2bfloat16(v.z - __bfloat162float(hz)),
                                __float2bfloat16(v.w - __bfloat162float(hw)));
    hi = H.u; lo = L.u;
}

// ---- one GEMM phase: dst = tanh([x|h] @ Wcat + bias), 64x64 tile ----
template <bool GATHER>
__device__ __forceinline__ void do_phase(
    unsigned char *smem_raw, uint32_t sb,
    const int *__restrict__ tok32, int tokStride, int t,
    const float *__restrict__ xsrc,          // emb (GATHER) or h0_new
    const float *__restrict__ hprev,
    const __nv_bfloat16 *__restrict__ Bw_hi,
    const __nv_bfloat16 *__restrict__ Bw_lo,
    const float *__restrict__ bias,
    float *__restrict__ dst, int row0, int col0)
{
    const int tid = threadIdx.x, lane = tid & 31, wid = tid >> 5;
    const int wm = wid & 3, wn = wid >> 2;
    int *toks = (int *)(smem_raw + TOKS);

    if (GATHER && tid < 64)
        toks[tid] = tok32[((size_t)(row0 + tid) * T_SZ + t) * tokStride];
    __syncthreads();

    float4 pfA[4];     // A chunk: 64 rows x 16 float4/row = 1024 vec (4/thread)
    uint4  pfBh[2], pfBl[2];  // B chunk: 64 rows x 8 uint4/row = 512 vec

    auto ldgA = [&](int c) {
        const int kb = c * 64;
        const bool xp = (kb < U_SZ);
        const int kk = xp ? kb : kb - U_SZ;
#pragma unroll
        for (int i = 0; i < 4; i++) {
            int idx = tid + i * NTHR;          // 0..1023
            int r = idx >> 4, kq = idx & 15;   // r: 0..63, kq: 0..15
            const float *p;
            if (xp) {
                if (GATHER) p = xsrc + (size_t)toks[r] * U_SZ + kk + kq * 4;
                else        p = xsrc + (size_t)(row0 + r) * U_SZ + kk + kq * 4;
            } else          p = hprev + (size_t)(row0 + r) * U_SZ + kk + kq * 4;
            pfA[i] = (xp && GATHER) ? __ldg((const float4 *)p)
                                    : __ldcg((const float4 *)p);
        }
    };
    auto ldgB = [&](int c) {
        const int kb = c * 64;
#pragma unroll
        for (int i = 0; i < 2; i++) {
            int idx = tid + i * NTHR;          // 0..511
            int n = idx >> 3, kq = idx & 7;    // n: 0..63, kq: 0..7
            size_t o = (size_t)(col0 + n) * KTOT + kb + kq * 8;
            pfBh[i] = __ldg((const uint4 *)(Bw_hi + o));
            pfBl[i] = __ldg((const uint4 *)(Bw_lo + o));
        }
    };
    auto sts = [&]() {
#pragma unroll
        for (int i = 0; i < 4; i++) {
            int idx = tid + i * NTHR;
            int r = idx >> 4, kq = idx & 15;
            uint2 hi, lo;
            split4(pfA[i], hi, lo);
            *(uint2 *)(smem_raw + A_HI + r * 144 + kq * 8) = hi;  // <=120+8
            *(uint2 *)(smem_raw + A_LO + r * 144 + kq * 8) = lo;
        }
#pragma unroll
        for (int i = 0; i < 2; i++) {
            int idx = tid + i * NTHR;
            int n = idx >> 3, kq = idx & 7;
            *(uint4 *)(smem_raw + B_HI + n * 144 + kq * 16) = pfBh[i];
            *(uint4 *)(smem_raw + B_LO + n * 144 + kq * 16) = pfBl[i];
        }
    };

    float acc[4][4];
#pragma unroll
    for (int i = 0; i < 4; i++)
#pragma unroll
        for (int j = 0; j < 4; j++) acc[i][j] = 0.f;

    // lane-fixed ldmatrix bases (16x16 tiles; x4 = 4 8x8 matrices)
    const uint32_t aHi = sb + A_HI + (wm * 16 + (lane & 15)) * 144 + (lane >> 4) * 16;
    const uint32_t aLo = aHi + (A_LO - A_HI);
    const int nrow = wn * 32 + (lane & 7) + ((lane >> 4) << 3);
    const uint32_t b0Hi = sb + B_HI + nrow * 144 + ((lane >> 3) & 1) * 16;
    const uint32_t b1Hi = b0Hi + 16 * 144;
    const uint32_t b0Lo = b0Hi + (B_LO - B_HI);
    const uint32_t b1Lo = b1Hi + (B_LO - B_HI);

    ldgA(0); ldgB(0);
    sts();
    __syncthreads();

#pragma unroll 1
    for (int c = 0; c < 16; c++) {
        if (c < 15) { ldgA(c + 1); ldgB(c + 1); }
#pragma unroll
        for (int ks = 0; ks < 4; ks++) {       // 4 k-steps of 16 (chunk = 64)
            uint32_t ah[4], al[4], bh0[4], bh1[4], bl0[4], bl1[4];
            LDSM4(ah, aHi + ks * 32);
            LDSM4(al, aLo + ks * 32);
            LDSM4(bh0, b0Hi + ks * 32);
            LDSM4(bh1, b1Hi + ks * 32);
            LDSM4(bl0, b0Lo + ks * 32);
            LDSM4(bl1, b1Lo + ks * 32);
            // 3 passes: hi*hi + lo*hi + hi*lo
            mma_bf16(acc[0], ah, bh0[0], bh0[1]);
            mma_bf16(acc[0], al, bh0[0], bh0[1]);
            mma_bf16(acc[0], ah, bl0[0], bl0[1]);
            mma_bf16(acc[1], ah, bh0[2], bh0[3]);
            mma_bf16(acc[1], al, bh0[2], bh0[3]);
            mma_bf16(acc[1], ah, bl0[2], bl0[3]);
            mma_bf16(acc[2], ah, bh1[0], bh1[1]);
            mma_bf16(acc[2], al, bh1[0], bh1[1]);
            mma_bf16(acc[2], ah, bl1[0], bl1[1]);
            mma_bf16(acc[3], ah, bh1[2], bh1[3]);
            mma_bf16(acc[3], al, bh1[2], bh1[3]);
            mma_bf16(acc[3], ah, bl1[2], bl1[3]);
        }
        __syncthreads();
        if (c < 15) { sts(); __syncthreads(); }
    }

    // epilogue: bias + tanh -> fp32 h
    const int mrow = row0 + wm * 16 + (lane >> 2);
    const int ncol = col0 + wn * 32 + 2 * (lane & 3);
#pragma unroll
    for (int nt = 0; nt < 4; nt++) {
        int n = ncol + nt * 8;
        float bv0 = __ldg(bias + n), bv1 = __ldg(bias + n + 1);
        float2 v0 = make_float2(tanhf(acc[nt][0] + bv0), tanhf(acc[nt][1] + bv1));
        float2 v1 = make_float2(tanhf(acc[nt][2] + bv0), tanhf(acc[nt][3] + bv1));
        *(float2 *)(dst + (size_t)mrow * U_SZ + n) = v0;
        *(float2 *)(dst + (size_t)(mrow + 8) * U_SZ + n) = v1;
    }
}

extern "C" __global__ void __launch_bounds__(NTHR, 1)
rnn_kernel(const int *__restrict__ tok32,
           const float *__restrict__ emb,
           const float *__restrict__ W0x, const float *__restrict__ W0h,
           const float *__restrict__ b0,
           const float *__restrict__ W1x, const float *__restrict__ W1h,
           const float *__restrict__ b1,
           const float *__restrict__ Wout, const float *__restrict__ bout,
           float *__restrict__ out)
{
    __shared__ __align__(128) unsigned char smem_raw[SM_BYTES];
    const uint32_t sb = smem_u32(smem_raw);
    const int tid = threadIdx.x, wid = tid >> 5, lane = tid & 31;
    const int cta = blockIdx.x;
    const int row0 = (cta >> 3) * 64;   // 16 row tiles
    const int col0 = (cta & 7) * 64;    //  8 col tiles
    const int gtid = cta * NTHR + tid, gstride = NCTA * NTHR;

    unsigned barBase = 0;
    if (tid == 0) barBase = *(volatile unsigned *)&g_gen;
    unsigned nb = 0;

    // token dtype autodetect (proven R3)
    __shared__ int s_stride;
    if (tid == 0) {
        bool hz = true;
#pragma unroll 1
        for (int i = 0; i < 32; i++)
            if (__ldg(tok32 + 2 * i + 1) != 0) { hz = false; break; }
        s_stride = hz ? 2 : 1;
    }
    __syncthreads();
    const int tokStride = s_stride;

    // ---- per-launch prep: weight transpose+split; zero h[0] ----
    for (int i = gtid; i < U_SZ * KTOT; i += gstride) {
        int n = i >> 10, k = i & 1023;   // write coalesced at [n*1024+k]
        float v0 = (k < U_SZ) ? __ldg(W0x + (size_t)k * U_SZ + n)
                              : __ldg(W0h + (size_t)(k - U_SZ) * U_SZ + n);
        float v1 = (k < U_SZ) ? __ldg(W1x + (size_t)k * U_SZ + n)
                              : __ldg(W1h + (size_t)(k - U_SZ) * U_SZ + n);
        __nv_bfloat16 h0 = __float2bfloat16(v0), h1 = __float2bfloat16(v1);
        g_Bhi[0][i] = h0;
        g_Blo[0][i] = __float2bfloat16(v0 - __bfloat162float(h0));
        g_Bhi[1][i] = h1;
        g_Blo[1][i] = __float2bfloat16(v1 - __bfloat162float(h1));
    }
    for (int i = gtid; i < B_SZ * U_SZ; i += gstride) {
        g_h0[0][i] = 0.f;
        g_h1[0][i] = 0.f;
    }
    grid_barrier(barBase, ++nb);

    // ---- recurrence: 160 phases ----
    for (int t = 0; t < T_SZ; t++) {
        int po = t & 1, pn = po ^ 1;
        do_phase<true >(smem_raw, sb, tok32, tokStride, t,
                        emb, g_h0[po], g_Bhi[0], g_Blo[0], b0,
                        g_h0[pn], row0, col0);
        grid_barrier(barBase, ++nb);
        do_phase<false>(smem_raw, sb, nullptr, 1, 0,
                        g_h0[pn], g_h1[po], g_Bhi[1], g_Blo[1], b1,
                        g_h1[pn], row0, col0);
        grid_barrier(barBase, ++nb);
    }

    // ---- final dense + sigmoid (h1 final in buffer 0 after t=79) ----
    {
        int b = cta * 8 + wid;              // 128 CTAs x 8 warps = 1024 rows
        const float *h1f = g_h1[0];
        float s = 0.f;
#pragma unroll
        for (int j = 0; j < 16; j++) {
            int k = lane + 32 * j;
            s += __ldcg(h1f + (size_t)b * U_SZ + k) * __ldg(Wout + k);
        }
#pragma unroll
        for (int off = 16; off; off >>= 1)
            s += __shfl_down_sync(0xffffffffu, s, off);
        if (lane == 0) {
            float z = s + __ldg(bout);
            out[b] = 1.f / (1.f + expf(-z));
        }
    }
}

extern "C" void kernel_launch(void *const *d_in, const int *in_sizes, int n_in,
                              void *d_out, int out_size)
{
    const int   *inputs = (const int *)d_in[0];
    const float *emb  = (const float *)d_in[1];
    const float *W0x  = (const float *)d_in[2];
    const float *W0h  = (const float *)d_in[3];
    const float *b0   = (const float *)d_in[4];
    const float *W1x  = (const float *)d_in[5];
    const float *W1h  = (const float *)d_in[6];
    const float *b1   = (const float *)d_in[7];
    const float *Wout = (const float *)d_in[8];
    const float *bout = (const float *)d_in[9];
    rnn_kernel<<<NCTA, NTHR>>>(inputs, emb, W0x, W0h, b0, W1x, W1h, b1,
                               Wout, bout, (float *)d_out);
}

// round 13
// speedup vs baseline: 6.8524x; 1.2755x over previous
#include <cuda_runtime.h>
#include <cuda_bf16.h>
#include <cstdint>

// ============================================================================
// 2-layer SimpleRNN, mma.sync bf16 hi/lo 3-pass, f32 accum.
// Split-grid pipeline: CTAs 0-63 run cell0 chain, CTAs 64-127 run cell1 one
// step behind -> 81 grid-barrier periods (was 160). CTA tile 128x64,
// warp tile 32x32. cp.async triple-buffered staging with the canonical
// wait -> syncthreads -> issue ordering (R12's issue-before-sync raced).
// ============================================================================

#define NCTA  128
#define NTHR  256
#define B_SZ  1024
#define T_SZ  80
#define U_SZ  512
#define KTOT  1024
#define VOCAB 50000

// smem (dynamic): per buffer: A 128 rows x 144B (hi,lo), B 64 rows x 144B (hi,lo)
#define AH    0
#define AL    18432
#define BH    36864
#define BL    46080
#define BUF_SZ 55296
#define TOKS  (3 * BUF_SZ)             // 165888
#define SM_TOTAL (TOKS + 512)          // 166400

// ---- global scratch (static __device__) ----
__device__ __nv_bfloat16 g_Xhi[VOCAB * U_SZ];
__device__ __nv_bfloat16 g_Xlo[VOCAB * U_SZ];
__device__ __nv_bfloat16 g_Bhi[2][U_SZ * KTOT];   // [cell][n*1024+k] = Wcat[k][n]
__device__ __nv_bfloat16 g_Blo[2][U_SZ * KTOT];
__device__ __nv_bfloat16 g_H0hi[2][B_SZ * U_SZ], g_H0lo[2][B_SZ * U_SZ];
__device__ __nv_bfloat16 g_H1hi[2][B_SZ * U_SZ], g_H1lo[2][B_SZ * U_SZ];
__device__ unsigned g_arrive = 0, g_gen = 0;

__device__ __forceinline__ uint32_t smem_u32(const void *p) {
    uint32_t a;
    asm("{ .reg .u64 t; cvta.to.shared.u64 t, %1; cvt.u32.u64 %0, t; }"
        : "=r"(a) : "l"(p));
    return a;
}
#define LDSM4(r, a) \
    asm volatile("ldmatrix.sync.aligned.m8n8.x4.shared.b16 {%0,%1,%2,%3}, [%4];" \
        : "=r"((r)[0]), "=r"((r)[1]), "=r"((r)[2]), "=r"((r)[3]) : "r"(a))

__device__ __forceinline__ void mma_bf16(float *d, const uint32_t *a,
                                         uint32_t b0, uint32_t b1) {
    asm volatile(
        "mma.sync.aligned.m16n8k16.row.col.f32.bf16.bf16.f32 "
        "{%0,%1,%2,%3}, {%4,%5,%6,%7}, {%8,%9}, {%0,%1,%2,%3};"
        : "+f"(d[0]), "+f"(d[1]), "+f"(d[2]), "+f"(d[3])
        : "r"(a[0]), "r"(a[1]), "r"(a[2]), "r"(a[3]), "r"(b0), "r"(b1));
}
__device__ __forceinline__ void cpa16(uint32_t s, const void *g) {
    asm volatile("cp.async.cg.shared.global [%0], [%1], 16;" :: "r"(s), "l"(g));
}
#define CPA_COMMIT() asm volatile("cp.async.commit_group;" ::: "memory")

__device__ __forceinline__ void grid_barrier(unsigned barBase, unsigned n) {
    __syncthreads();
    if (threadIdx.x == 0) {
        __threadfence();
        unsigned rank = atomicAdd(&g_arrive, 1);
        if (rank == NCTA - 1) {
            g_arrive = 0;
            __threadfence();
            atomicAdd(&g_gen, 1);
        } else {
            unsigned target = barBase + n;
            while ((int)(*(volatile unsigned *)&g_gen - target) < 0) { }
            __threadfence();
        }
    }
    __syncthreads();
}

__device__ __forceinline__ void split2(float x, float y,
                                       uint32_t &hi, uint32_t &lo) {
    __nv_bfloat16 hx = __float2bfloat16(x), hy = __float2bfloat16(y);
    union { uint32_t u; __nv_bfloat162 b; } H, L;
    H.b = __halves2bfloat162(hx, hy);
    L.b = __halves2bfloat162(__float2bfloat16(x - __bfloat162float(hx)),
                             __float2bfloat16(y - __bfloat162float(hy)));
    hi = H.u; lo = L.u;
}

// ---- one GEMM phase: dst = tanh([x|h] @ Wcat + bias), 128x64 tile ----
template <bool GATHER>
__device__ __forceinline__ void do_phase(
    unsigned char *dsm, uint32_t sb,
    const int *__restrict__ tok32, int tokStride, int t,
    const __nv_bfloat16 *__restrict__ xhi, const __nv_bfloat16 *__restrict__ xlo,
    const __nv_bfloat16 *__restrict__ hhi, const __nv_bfloat16 *__restrict__ hlo,
    const __nv_bfloat16 *__restrict__ bwh, const __nv_bfloat16 *__restrict__ bwl,
    const float *__restrict__ bias,
    __nv_bfloat16 *__restrict__ dhi, __nv_bfloat16 *__restrict__ dlo,
    int row0, int col0)
{
    const int tid = threadIdx.x, lane = tid & 31, wid = tid >> 5;
    const int wm = wid & 3, wn = wid >> 2;
    int *toks = (int *)(dsm + TOKS);

    if (GATHER) {
        if (tid < 128)
            toks[tid] = tok32[((size_t)(row0 + tid) * T_SZ + t) * tokStride];
        __syncthreads();
    }

    auto issue = [&](int c) {
        const uint32_t bufb = sb + (uint32_t)(c % 3) * BUF_SZ;
        const int kb = c * 64;
        const bool xp = (kb < U_SZ);
        const int kk = xp ? kb : kb - U_SZ;
        const __nv_bfloat16 *shi = xp ? xhi : hhi;
        const __nv_bfloat16 *slo = xp ? xlo : hlo;
#pragma unroll
        for (int i = 0; i < 4; i++) {            // A: 128 rows x 8 x 16B
            int idx = tid + i * NTHR;
            int r = idx >> 3, q = idx & 7;
            size_t go = (GATHER && xp) ? (size_t)toks[r] * U_SZ + kk + q * 8
                                       : (size_t)(row0 + r) * U_SZ + kk + q * 8;
            uint32_t so = bufb + AH + r * 144 + q * 16;
            cpa16(so, shi + go);
            cpa16(so + (AL - AH), slo + go);
        }
#pragma unroll
        for (int i = 0; i < 2; i++) {            // B: 64 rows x 8 x 16B
            int idx = tid + i * NTHR;
            int n = idx >> 3, q = idx & 7;
            size_t go = (size_t)(col0 + n) * KTOT + kb + q * 8;
            uint32_t so = bufb + BH + n * 144 + q * 16;
            cpa16(so, bwh + go);
            cpa16(so + (BL - BH), bwl + go);
        }
        CPA_COMMIT();
    };

    float acc[2][4][4];
#pragma unroll
    for (int i = 0; i < 2; i++)
#pragma unroll
        for (int j = 0; j < 4; j++)
#pragma unroll
            for (int k = 0; k < 4; k++) acc[i][j][k] = 0.f;

    // lane-fixed ldmatrix offsets (relative to buffer base)
    const uint32_t oA = AH + (wm * 32 + (lane & 15)) * 144 + (lane >> 4) * 16;
    const uint32_t oB = BH + (wn * 32 + (lane & 7) + ((lane >> 4) << 3)) * 144
                        + ((lane >> 3) & 1) * 16;

    issue(0);
    issue(1);
#pragma unroll 1
    for (int c = 0; c < 16; c++) {
        // groups complete in order: <=1 pending => group c landed
        if (c < 15) asm volatile("cp.async.wait_group 1;" ::: "memory");
        else        asm volatile("cp.async.wait_group 0;" ::: "memory");
        __syncthreads();   // all warps done with buffer (c-1)%3, buffer c%3 visible
        if (c < 14) issue(c + 2);   // refill (c-1)%3 -- safe after the barrier

        const uint32_t bb = sb + (uint32_t)(c % 3) * BUF_SZ;
#pragma unroll
        for (int ks = 0; ks < 4; ks++) {
            uint32_t ah0[4], ah1[4], al0[4], al1[4];
            uint32_t bh0[4], bh1[4], bl0[4], bl1[4];
            const uint32_t a0 = bb + oA + ks * 32;
            const uint32_t b0 = bb + oB + ks * 32;
            LDSM4(ah0, a0);
            LDSM4(ah1, a0 + 16 * 144);
            LDSM4(al0, a0 + (AL - AH));
            LDSM4(al1, a0 + (AL - AH) + 16 * 144);
            LDSM4(bh0, b0);
            LDSM4(bh1, b0 + 16 * 144);
            LDSM4(bl0, b0 + (BL - BH));
            LDSM4(bl1, b0 + (BL - BH) + 16 * 144);
            // 3 passes: hi*hi + lo*hi + hi*lo  (mt = 0)
            mma_bf16(acc[0][0], ah0, bh0[0], bh0[1]);
            mma_bf16(acc[0][0], al0, bh0[0], bh0[1]);
            mma_bf16(acc[0][0], ah0, bl0[0], bl0[1]);
            mma_bf16(acc[0][1], ah0, bh0[2], bh0[3]);
            mma_bf16(acc[0][1], al0, bh0[2], bh0[3]);
            mma_bf16(acc[0][1], ah0, bl0[2], bl0[3]);
            mma_bf16(acc[0][2], ah0, bh1[0], bh1[1]);
            mma_bf16(acc[0][2], al0, bh1[0], bh1[1]);
            mma_bf16(acc[0][2], ah0, bl1[0], bl1[1]);
            mma_bf16(acc[0][3], ah0, bh1[2], bh1[3]);
            mma_bf16(acc[0][3], al0, bh1[2], bh1[3]);
            mma_bf16(acc[0][3], ah0, bl1[2], bl1[3]);
            // mt = 1
            mma_bf16(acc[1][0], ah1, bh0[0], bh0[1]);
            mma_bf16(acc[1][0], al1, bh0[0], bh0[1]);
            mma_bf16(acc[1][0], ah1, bl0[0], bl0[1]);
            mma_bf16(acc[1][1], ah1, bh0[2], bh0[3]);
            mma_bf16(acc[1][1], al1, bh0[2], bh0[3]);
            mma_bf16(acc[1][1], ah1, bl0[2], bl0[3]);
            mma_bf16(acc[1][2], ah1, bh1[0], bh1[1]);
            mma_bf16(acc[1][2], al1, bh1[0], bh1[1]);
            mma_bf16(acc[1][2], ah1, bl1[0], bl1[1]);
            mma_bf16(acc[1][3], ah1, bh1[2], bh1[3]);
            mma_bf16(acc[1][3], al1, bh1[2], bh1[3]);
            mma_bf16(acc[1][3], ah1, bl1[2], bl1[3]);
        }
    }

    // epilogue: bias + tanh -> bf16 hi/lo h state
#pragma unroll
    for (int mt = 0; mt < 2; mt++) {
        const int mrow = row0 + wm * 32 + mt * 16 + (lane >> 2);
#pragma unroll
        for (int oct = 0; oct < 4; oct++) {
            const int ncol = col0 + wn * 32 + oct * 8 + 2 * (lane & 3);
            float bv0 = __ldg(bias + ncol), bv1 = __ldg(bias + ncol + 1);
            float v0 = tanhf(acc[mt][oct][0] + bv0);
            float v1 = tanhf(acc[mt][oct][1] + bv1);
            float v2 = tanhf(acc[mt][oct][2] + bv0);
            float v3 = tanhf(acc[mt][oct][3] + bv1);
            uint32_t hi, lo;
            split2(v0, v1, hi, lo);
            *(uint32_t *)(dhi + (size_t)mrow * U_SZ + ncol) = hi;
            *(uint32_t *)(dlo + (size_t)mrow * U_SZ + ncol) = lo;
            split2(v2, v3, hi, lo);
            *(uint32_t *)(dhi + (size_t)(mrow + 8) * U_SZ + ncol) = hi;
            *(uint32_t *)(dlo + (size_t)(mrow + 8) * U_SZ + ncol) = lo;
        }
    }
}

extern "C" __global__ void __launch_bounds__(NTHR, 1)
rnn_kernel(const int *__restrict__ tok32,
           const float *__restrict__ emb,
           const float *__restrict__ W0x, const float *__restrict__ W0h,
           const float *__restrict__ b0,
           const float *__restrict__ W1x, const float *__restrict__ W1h,
           const float *__restrict__ b1,
           const float *__restrict__ Wout, const float *__restrict__ bout,
           float *__restrict__ out)
{
    extern __shared__ __align__(128) unsigned char dsm[];
    const uint32_t sb = smem_u32(dsm);
    const int tid = threadIdx.x, wid = tid >> 5, lane = tid & 31;
    const int cta = blockIdx.x;
    const bool cell0 = (cta < 64);
    const int local = cell0 ? cta : cta - 64;
    const int row0 = (local >> 3) * 128;   // 8 row tiles of 128
    const int col0 = (local & 7) * 64;     // 8 col tiles of 64
    const int gtid = cta * NTHR + tid, gstride = NCTA * NTHR;

    unsigned barBase = 0;
    if (tid == 0) barBase = *(volatile unsigned *)&g_gen;
    unsigned nb = 0;

    // token dtype autodetect (proven)
    __shared__ int s_stride;
    if (tid == 0) {
        bool hz = true;
#pragma unroll 1
        for (int i = 0; i < 32; i++)
            if (__ldg(tok32 + 2 * i + 1) != 0) { hz = false; break; }
        s_stride = hz ? 2 : 1;
    }
    __syncthreads();
    const int tokStride = s_stride;

    // ---- per-launch prep ----
    for (int i = gtid; i < VOCAB * U_SZ / 4; i += gstride) {
        float4 v = __ldg((const float4 *)emb + i);
        uint32_t h0, l0, h1, l1;
        split2(v.x, v.y, h0, l0);
        split2(v.z, v.w, h1, l1);
        *(uint2 *)(g_Xhi + (size_t)i * 4) = make_uint2(h0, h1);
        *(uint2 *)(g_Xlo + (size_t)i * 4) = make_uint2(l0, l1);
    }
    for (int i = gtid; i < U_SZ * KTOT; i += gstride) {
        int n = i & 511, k = i >> 9;
        float v0 = (k < U_SZ) ? __ldg(W0x + (size_t)k * U_SZ + n)
                              : __ldg(W0h + (size_t)(k - U_SZ) * U_SZ + n);
        float v1 = (k < U_SZ) ? __ldg(W1x + (size_t)k * U_SZ + n)
                              : __ldg(W1h + (size_t)(k - U_SZ) * U_SZ + n);
        size_t o = (size_t)n * KTOT + k;
        __nv_bfloat16 h0 = __float2bfloat16(v0), h1 = __float2bfloat16(v1);
        g_Bhi[0][o] = h0;
        g_Blo[0][o] = __float2bfloat16(v0 - __bfloat162float(h0));
        g_Bhi[1][o] = h1;
        g_Blo[1][o] = __float2bfloat16(v1 - __bfloat162float(h1));
    }
    for (int i = gtid; i < B_SZ * U_SZ / 8; i += gstride) {
        ((uint4 *)g_H0hi[0])[i] = make_uint4(0, 0, 0, 0);
        ((uint4 *)g_H0lo[0])[i] = make_uint4(0, 0, 0, 0);
        ((uint4 *)g_H1hi[0])[i] = make_uint4(0, 0, 0, 0);
        ((uint4 *)g_H1lo[0])[i] = make_uint4(0, 0, 0, 0);
    }
    grid_barrier(barBase, ++nb);

    // ---- pipelined recurrence: 81 periods ----
    // cell0 at period p computes t=p; cell1 computes t=p-1.
    // h(t) written to buf[(t&1)^1]; h(t-1) read from buf[t&1].
    for (int p = 0; p <= T_SZ; p++) {
        if (cell0) {
            if (p <= T_SZ - 1) {
                int t = p, rb = t & 1;
                do_phase<true>(dsm, sb, tok32, tokStride, t,
                               g_Xhi, g_Xlo,
                               g_H0hi[rb], g_H0lo[rb],
                               g_Bhi[0], g_Blo[0], b0,
                               g_H0hi[rb ^ 1], g_H0lo[rb ^ 1], row0, col0);
            }
        } else {
            if (p >= 1) {
                int t = p - 1, rb = t & 1;
                do_phase<false>(dsm, sb, nullptr, 1, 0,
                                g_H0hi[rb ^ 1], g_H0lo[rb ^ 1],   // x = h0(t)
                                g_H1hi[rb], g_H1lo[rb],           // h1(t-1)
                                g_Bhi[1], g_Blo[1], b1,
                                g_H1hi[rb ^ 1], g_H1lo[rb ^ 1], row0, col0);
            }
        }
        grid_barrier(barBase, ++nb);
    }

    // ---- final dense + sigmoid: h1(79) in buffer 0; L1-bypass reads ----
    {
        int b = cta * 8 + wid;               // 1024 rows
        const __nv_bfloat16 *fh = g_H1hi[0], *fl = g_H1lo[0];
        float s = 0.f;
#pragma unroll
        for (int j = 0; j < 8; j++) {
            int k = lane * 2 + 64 * j;
            size_t o = (size_t)b * U_SZ + k;
            uint32_t uh = __ldcg((const uint32_t *)(fh + o));
            uint32_t ul = __ldcg((const uint32_t *)(fl + o));
            __nv_bfloat162 vh = *reinterpret_cast<__nv_bfloat162 *>(&uh);
            __nv_bfloat162 vl = *reinterpret_cast<__nv_bfloat162 *>(&ul);
            s += (__bfloat162float(vh.x) + __bfloat162float(vl.x)) * __ldg(Wout + k);
            s += (__bfloat162float(vh.y) + __bfloat162float(vl.y)) * __ldg(Wout + k + 1);
        }
#pragma unroll
        for (int off = 16; off; off >>= 1)
            s += __shfl_down_sync(0xffffffffu, s, off);
        if (lane == 0) {
            float z = s + __ldg(bout);
            out[b] = 1.f / (1.f + expf(-z));
        }
    }
}

extern "C" void kernel_launch(void *const *d_in, const int *in_sizes, int n_in,
                              void *d_out, int out_size)
{
    const int   *inputs = (const int *)d_in[0];
    const float *emb  = (const float *)d_in[1];
    const float *W0x  = (const float *)d_in[2];
    const float *W0h  = (const float *)d_in[3];
    const float *b0   = (const float *)d_in[4];
    const float *W1x  = (const float *)d_in[5];
    const float *W1h  = (const float *)d_in[6];
    const float *b1   = (const float *)d_in[7];
    const float *Wout = (const float *)d_in[8];
    const float *bout = (const float *)d_in[9];
    cudaFuncSetAttribute(rnn_kernel, cudaFuncAttributeMaxDynamicSharedMemorySize,
                         SM_TOTAL);
    rnn_kernel<<<NCTA, NTHR, SM_TOTAL>>>(inputs, emb, W0x, W0h, b0,
                                         W1x, W1h, b1, Wout, bout,
                                         (float *)d_out);
}

// round 14
// speedup vs baseline: 13.7734x; 2.0100x over previous
#include <cuda_runtime.h>
#include <cuda_fp16.h>
#include <cstdint>

// ============================================================================
// 2-layer SimpleRNN, mma.sync fp16 single-pass (f32 accum).
// fp16 (10 mantissa bits) replaces the bf16 hi/lo 3-pass scheme: 1/3 the MMAs,
// 1/2 the operand bytes. Split-grid pipeline (cell0: CTAs 0-63, cell1: 64-127,
// one step behind) -> 81 grid-barrier periods. CTA tile 128x64, warp 32x32.
// cp.async triple-buffered, chunk K=128, wait -> sync -> issue ordering.
// ============================================================================

#define NCTA  128
#define NTHR  256
#define B_SZ  1024
#define T_SZ  80
#define U_SZ  512
#define KTOT  1024
#define VOCAB 50000

// smem: row stride 272B = 256B data (128 fp16) + 16B pad (LDSM conflict-free)
#define AOFF  0                        // A: 128 rows x 272B = 34816
#define BOFF  34816                    // B: 64 rows x 272B = 17408
#define BUF_SZ 52224
#define TOKS  (3 * BUF_SZ)             // 156672
#define SM_TOTAL (TOKS + 512)

// ---- global scratch (static __device__) ----
__device__ __half g_X[VOCAB * U_SZ];              // emb, fp16
__device__ __half g_B[2][U_SZ * KTOT];            // [cell][n*1024+k] = Wcat[k][n]
__device__ __half g_H0[2][B_SZ * U_SZ];           // h state, fp16, ping-pong
__device__ __half g_H1[2][B_SZ * U_SZ];
__device__ unsigned g_arrive = 0, g_gen = 0;

__device__ __forceinline__ uint32_t smem_u32(const void *p) {
    uint32_t a;
    asm("{ .reg .u64 t; cvta.to.shared.u64 t, %1; cvt.u32.u64 %0, t; }"
        : "=r"(a) : "l"(p));
    return a;
}
#define LDSM4(r, a) \
    asm volatile("ldmatrix.sync.aligned.m8n8.x4.shared.b16 {%0,%1,%2,%3}, [%4];" \
        : "=r"((r)[0]), "=r"((r)[1]), "=r"((r)[2]), "=r"((r)[3]) : "r"(a))

__device__ __forceinline__ void mma_f16(float *d, const uint32_t *a,
                                        uint32_t b0, uint32_t b1) {
    asm volatile(
        "mma.sync.aligned.m16n8k16.row.col.f32.f16.f16.f32 "
        "{%0,%1,%2,%3}, {%4,%5,%6,%7}, {%8,%9}, {%0,%1,%2,%3};"
        : "+f"(d[0]), "+f"(d[1]), "+f"(d[2]), "+f"(d[3])
        : "r"(a[0]), "r"(a[1]), "r"(a[2]), "r"(a[3]), "r"(b0), "r"(b1));
}
__device__ __forceinline__ void cpa16(uint32_t s, const void *g) {
    asm volatile("cp.async.cg.shared.global [%0], [%1], 16;" :: "r"(s), "l"(g));
}
#define CPA_COMMIT() asm volatile("cp.async.commit_group;" ::: "memory")

__device__ __forceinline__ void grid_barrier(unsigned barBase, unsigned n) {
    __syncthreads();
    if (threadIdx.x == 0) {
        __threadfence();
        unsigned rank = atomicAdd(&g_arrive, 1);
        if (rank == NCTA - 1) {
            g_arrive = 0;
            __threadfence();
            atomicAdd(&g_gen, 1);
        } else {
            unsigned target = barBase + n;
            while ((int)(*(volatile unsigned *)&g_gen - target) < 0) { }
            __threadfence();
        }
    }
    __syncthreads();
}

// ---- one GEMM phase: dst = tanh([x|h] @ Wcat + bias), 128x64 tile ----
template <bool GATHER>
__device__ __forceinline__ void do_phase(
    unsigned char *dsm, uint32_t sb,
    const int *__restrict__ tok32, int tokStride, int t,
    const __half *__restrict__ xsrc,         // emb (GATHER) or h0_new
    const __half *__restrict__ hprev,
    const __half *__restrict__ bw,           // weights [n][k]
    const float *__restrict__ bias,
    __half *__restrict__ dst, int row0, int col0)
{
    const int tid = threadIdx.x, lane = tid & 31, wid = tid >> 5;
    const int wm = wid & 3, wn = wid >> 2;
    int *toks = (int *)(dsm + TOKS);

    if (GATHER) {
        if (tid < 128)
            toks[tid] = tok32[((size_t)(row0 + tid) * T_SZ + t) * tokStride];
        __syncthreads();
    }

    auto issue = [&](int c) {                 // chunk c: k = c*128 .. +127
        const uint32_t bufb = sb + (uint32_t)(c % 3) * BUF_SZ;
        const int kb = c * 128;
        const bool xp = (kb < U_SZ);
        const int kk = xp ? kb : kb - U_SZ;
        const __half *src = xp ? xsrc : hprev;
#pragma unroll
        for (int i = 0; i < 8; i++) {         // A: 128 rows x 16 x 16B
            int idx = tid + i * NTHR;         // 0..2047
            int r = idx >> 4, q = idx & 15;
            size_t go = (GATHER && xp) ? (size_t)toks[r] * U_SZ + kk + q * 8
                                       : (size_t)(row0 + r) * U_SZ + kk + q * 8;
            cpa16(bufb + AOFF + r * 272 + q * 16, src + go);
        }
#pragma unroll
        for (int i = 0; i < 4; i++) {         // B: 64 rows x 16 x 16B
            int idx = tid + i * NTHR;         // 0..1023
            int n = idx >> 4, q = idx & 15;
            size_t go = (size_t)(col0 + n) * KTOT + kb + q * 8;
            cpa16(bufb + BOFF + n * 272 + q * 16, bw + go);
        }
        CPA_COMMIT();
    };

    float acc[2][4][4];
#pragma unroll
    for (int i = 0; i < 2; i++)
#pragma unroll
        for (int j = 0; j < 4; j++)
#pragma unroll
            for (int k = 0; k < 4; k++) acc[i][j][k] = 0.f;

    // lane-fixed ldmatrix offsets (relative to buffer base); b16 mapping proven
    const uint32_t oA = AOFF + (wm * 32 + (lane & 15)) * 272 + (lane >> 4) * 16;
    const uint32_t oB = BOFF + (wn * 32 + (lane & 7) + ((lane >> 4) << 3)) * 272
                        + ((lane >> 3) & 1) * 16;

    issue(0);
    issue(1);
#pragma unroll 1
    for (int c = 0; c < 8; c++) {
        // groups retire in order: <=1 pending => group c landed
        if (c < 7) asm volatile("cp.async.wait_group 1;" ::: "memory");
        else       asm volatile("cp.async.wait_group 0;" ::: "memory");
        __syncthreads();    // all warps done with buf (c-1)%3; buf c%3 visible
        if (c < 6) issue(c + 2);    // refill (c-1)%3 -- safe after barrier

        const uint32_t bb = sb + (uint32_t)(c % 3) * BUF_SZ;
#pragma unroll
        for (int ks = 0; ks < 8; ks++) {      // 8 k-steps of 16
            uint32_t a0[4], a1[4], b0[4], b1[4];
            const uint32_t aa = bb + oA + ks * 32;
            const uint32_t ba = bb + oB + ks * 32;
            LDSM4(a0, aa);
            LDSM4(a1, aa + 16 * 272);
            LDSM4(b0, ba);
            LDSM4(b1, ba + 16 * 272);
            mma_f16(acc[0][0], a0, b0[0], b0[1]);
            mma_f16(acc[0][1], a0, b0[2], b0[3]);
            mma_f16(acc[0][2], a0, b1[0], b1[1]);
            mma_f16(acc[0][3], a0, b1[2], b1[3]);
            mma_f16(acc[1][0], a1, b0[0], b0[1]);
            mma_f16(acc[1][1], a1, b0[2], b0[3]);
            mma_f16(acc[1][2], a1, b1[0], b1[1]);
            mma_f16(acc[1][3], a1, b1[2], b1[3]);
        }
    }

    // epilogue: bias + tanh -> fp16 h state
#pragma unroll
    for (int mt = 0; mt < 2; mt++) {
        const int mrow = row0 + wm * 32 + mt * 16 + (lane >> 2);
#pragma unroll
        for (int oct = 0; oct < 4; oct++) {
            const int ncol = col0 + wn * 32 + oct * 8 + 2 * (lane & 3);
            float bv0 = __ldg(bias + ncol), bv1 = __ldg(bias + ncol + 1);
            __half2 v0 = __floats2half2_rn(tanhf(acc[mt][oct][0] + bv0),
                                           tanhf(acc[mt][oct][1] + bv1));
            __half2 v1 = __floats2half2_rn(tanhf(acc[mt][oct][2] + bv0),
                                           tanhf(acc[mt][oct][3] + bv1));
            *(__half2 *)(dst + (size_t)mrow * U_SZ + ncol) = v0;
            *(__half2 *)(dst + (size_t)(mrow + 8) * U_SZ + ncol) = v1;
        }
    }
}

extern "C" __global__ void __launch_bounds__(NTHR, 1)
rnn_kernel(const int *__restrict__ tok32,
           const float *__restrict__ emb,
           const float *__restrict__ W0x, const float *__restrict__ W0h,
           const float *__restrict__ b0,
           const float *__restrict__ W1x, const float *__restrict__ W1h,
           const float *__restrict__ b1,
           const float *__restrict__ Wout, const float *__restrict__ bout,
           float *__restrict__ out)
{
    extern __shared__ __align__(128) unsigned char dsm[];
    const uint32_t sb = smem_u32(dsm);
    const int tid = threadIdx.x, wid = tid >> 5, lane = tid & 31;
    const int cta = blockIdx.x;
    const bool cell0 = (cta < 64);
    const int local = cell0 ? cta : cta - 64;
    const int row0 = (local >> 3) * 128;   // 8 row tiles of 128
    const int col0 = (local & 7) * 64;     // 8 col tiles of 64
    const int gtid = cta * NTHR + tid, gstride = NCTA * NTHR;

    unsigned barBase = 0;
    if (tid == 0) barBase = *(volatile unsigned *)&g_gen;
    unsigned nb = 0;

    // token dtype autodetect (proven)
    __shared__ int s_stride;
    if (tid == 0) {
        bool hz = true;
#pragma unroll 1
        for (int i = 0; i < 32; i++)
            if (__ldg(tok32 + 2 * i + 1) != 0) { hz = false; break; }
        s_stride = hz ? 2 : 1;
    }
    __syncthreads();
    const int tokStride = s_stride;

    // ---- per-launch prep ----
    // 1) emb -> fp16
    for (int i = gtid; i < VOCAB * U_SZ / 4; i += gstride) {
        float4 v = __ldg((const float4 *)emb + i);
        __half2 h0 = __floats2half2_rn(v.x, v.y);
        __half2 h1 = __floats2half2_rn(v.z, v.w);
        *(uint2 *)(g_X + (size_t)i * 4) =
            make_uint2(*(uint32_t *)&h0, *(uint32_t *)&h1);
    }
    // 2) weights: transpose to [n][k], fp16 (reads coalesced over n)
    for (int i = gtid; i < U_SZ * KTOT; i += gstride) {
        int n = i & 511, k = i >> 9;
        float v0 = (k < U_SZ) ? __ldg(W0x + (size_t)k * U_SZ + n)
                              : __ldg(W0h + (size_t)(k - U_SZ) * U_SZ + n);
        float v1 = (k < U_SZ) ? __ldg(W1x + (size_t)k * U_SZ + n)
                              : __ldg(W1h + (size_t)(k - U_SZ) * U_SZ + n);
        size_t o = (size_t)n * KTOT + k;
        g_B[0][o] = __float2half_rn(v0);
        g_B[1][o] = __float2half_rn(v1);
    }
    // 3) zero initial h (buffer 0: read at t=0)
    for (int i = gtid; i < B_SZ * U_SZ / 8; i += gstride) {
        ((uint4 *)g_H0[0])[i] = make_uint4(0, 0, 0, 0);
        ((uint4 *)g_H1[0])[i] = make_uint4(0, 0, 0, 0);
    }
    grid_barrier(barBase, ++nb);

    // ---- pipelined recurrence: 81 periods ----
    // cell0 at period p computes t=p; cell1 computes t=p-1.
    // h(t) written to buf[(t&1)^1]; h(t-1) read from buf[t&1].
    for (int p = 0; p <= T_SZ; p++) {
        if (cell0) {
            if (p <= T_SZ - 1) {
                int t = p, rb = t & 1;
                do_phase<true>(dsm, sb, tok32, tokStride, t,
                               g_X, g_H0[rb], g_B[0], b0,
                               g_H0[rb ^ 1], row0, col0);
            }
        } else {
            if (p >= 1) {
                int t = p - 1, rb = t & 1;
                do_phase<false>(dsm, sb, nullptr, 1, 0,
                                g_H0[rb ^ 1],      // x = h0(t)
                                g_H1[rb],          // h1(t-1)
                                g_B[1], b1,
                                g_H1[rb ^ 1], row0, col0);
            }
        }
        grid_barrier(barBase, ++nb);
    }

    // ---- final dense + sigmoid: h1(79) in buffer 0; L1-bypass reads ----
    {
        int b = cta * 8 + wid;               // 1024 rows
        const __half *fh = g_H1[0];
        float s = 0.f;
#pragma unroll
        for (int j = 0; j < 8; j++) {
            int k = lane * 2 + 64 * j;
            uint32_t u = __ldcg((const uint32_t *)(fh + (size_t)b * U_SZ + k));
            __half2 v = *reinterpret_cast<__half2 *>(&u);
            s += __half2float(v.x) * __ldg(Wout + k);
            s += __half2float(v.y) * __ldg(Wout + k + 1);
        }
#pragma unroll
        for (int off = 16; off; off >>= 1)
            s += __shfl_down_sync(0xffffffffu, s, off);
        if (lane == 0) {
            float z = s + __ldg(bout);
            out[b] = 1.f / (1.f + expf(-z));
        }
    }
}

extern "C" void kernel_launch(void *const *d_in, const int *in_sizes, int n_in,
                              void *d_out, int out_size)
{
    const int   *inputs = (const int *)d_in[0];
    const float *emb  = (const float *)d_in[1];
    const float *W0x  = (const float *)d_in[2];
    const float *W0h  = (const float *)d_in[3];
    const float *b0   = (const float *)d_in[4];
    const float *W1x  = (const float *)d_in[5];
    const float *W1h  = (const float *)d_in[6];
    const float *b1   = (const float *)d_in[7];
    const float *Wout = (const float *)d_in[8];
    const float *bout = (const float *)d_in[9];
    cudaFuncSetAttribute(rnn_kernel, cudaFuncAttributeMaxDynamicSharedMemorySize,
                         SM_TOTAL);
    rnn_kernel<<<NCTA, NTHR, SM_TOTAL>>>(inputs, emb, W0x, W0h, b0,
                                         W1x, W1h, b1, Wout, bout,
                                         (float *)d_out);
}

// round 16
// speedup vs baseline: 14.0310x; 1.0187x over previous
#include <cuda_runtime.h>
#include <cuda_fp16.h>
#include <cstdint>

// ============================================================================
// 2-layer SimpleRNN, mma.sync fp16 single-pass (f32 accum).
// R15: weights resident in smem for the whole launch (staged once);
// per-phase cp.async stages only A (K-chunks of 64, triple-buffered);
// cell0 pre-issues next phase's first emb chunks BEFORE the grid barrier;
// register double-buffered ldmatrix fragments pipeline LDSM against MMA.
// Split-grid pipeline (cell0: CTAs 0-63, cell1: 64-127) -> 81 periods.
// CTA tile 128x64, warp tile 32x32.
// ============================================================================

#define NCTA  128
#define NTHR  256
#define B_SZ  1024
#define T_SZ  80
#define U_SZ  512
#define KTOT  1024
#define VOCAB 50000

// smem layout
#define B_ROW 2064                       // 1024 fp16 + 16B pad (129*16: conflict-free)
#define BOFF  0                          // B: 64 rows x 2064 = 132096
#define AOFF  132096
#define A_ROW 144                        // 64 fp16 + 16B pad (9*16: conflict-free)
#define ABUF  (128 * A_ROW)              // 18432 per buffer, x3
#define TOKS  (AOFF + 3 * ABUF)          // 187392
#define SM_TOTAL (TOKS + 512)            // 187904

// ---- global scratch (static __device__) ----
__device__ __half g_X[VOCAB * U_SZ];              // emb, fp16
__device__ __half g_B[2][U_SZ * KTOT];            // [cell][n*1024+k] = Wcat[k][n]
__device__ __half g_H0[2][B_SZ * U_SZ];           // h state, fp16, ping-pong
__device__ __half g_H1[2][B_SZ * U_SZ];
__device__ unsigned g_arrive = 0, g_gen = 0;

__device__ __forceinline__ uint32_t smem_u32(const void *p) {
    uint32_t a;
    asm("{ .reg .u64 t; cvta.to.shared.u64 t, %1; cvt.u32.u64 %0, t; }"
        : "=r"(a) : "l"(p));
    return a;
}
#define LDSM4(r, a) \
    asm volatile("ldmatrix.sync.aligned.m8n8.x4.shared.b16 {%0,%1,%2,%3}, [%4];" \
        : "=r"((r)[0]), "=r"((r)[1]), "=r"((r)[2]), "=r"((r)[3]) : "r"(a))

__device__ __forceinline__ void mma_f16(float *d, const uint32_t *a,
                                        uint32_t b0, uint32_t b1) {
    asm volatile(
        "mma.sync.aligned.m16n8k16.row.col.f32.f16.f16.f32 "
        "{%0,%1,%2,%3}, {%4,%5,%6,%7}, {%8,%9}, {%0,%1,%2,%3};"
        : "+f"(d[0]), "+f"(d[1]), "+f"(d[2]), "+f"(d[3])
        : "r"(a[0]), "r"(a[1]), "r"(a[2]), "r"(a[3]), "r"(b0), "r"(b1));
}
__device__ __forceinline__ void cpa16(uint32_t s, const void *g) {
    asm volatile("cp.async.cg.shared.global [%0], [%1], 16;" :: "r"(s), "l"(g));
}
#define CPA_COMMIT() asm volatile("cp.async.commit_group;" ::: "memory")

__device__ __forceinline__ void grid_barrier(unsigned barBase, unsigned n) {
    __syncthreads();
    if (threadIdx.x == 0) {
        __threadfence();
        unsigned rank = atomicAdd(&g_arrive, 1);
        if (rank == NCTA - 1) {
            g_arrive = 0;
            __threadfence();
            atomicAdd(&g_gen, 1);
        } else {
            unsigned target = barBase + n;
            while ((int)(*(volatile unsigned *)&g_gen - target) < 0) { }
            __threadfence();
        }
    }
    __syncthreads();
}

// stage one A chunk (K=64) via cp.async; chunks 0-7: x part, 8-15: h part
template <bool GATHER>
__device__ __forceinline__ void issueA(
    uint32_t sb, const int *toks, int c,
    const __half *__restrict__ xsrc, const __half *__restrict__ hprev, int row0)
{
    const int tid = threadIdx.x;
    const uint32_t bufb = sb + AOFF + (uint32_t)(c % 3) * ABUF;
    const int kb = c * 64;
    const bool xp = (kb < U_SZ);
    const int kk = xp ? kb : kb - U_SZ;
    const __half *src = xp ? xsrc : hprev;
#pragma unroll
    for (int i = 0; i < 4; i++) {             // 128 rows x 8 x 16B = 1024 cpa
        int idx = tid + i * NTHR;
        int r = idx >> 3, q = idx & 7;
        size_t go = (GATHER && xp) ? (size_t)toks[r] * U_SZ + kk + q * 8
                                   : (size_t)(row0 + r) * U_SZ + kk + q * 8;
        cpa16(bufb + r * A_ROW + q * 16, src + go);
    }
    CPA_COMMIT();
}

// ---- one GEMM phase: dst = tanh([x|h] @ Wcat + bias), 128x64 tile ----
template <bool GATHER>
__device__ __forceinline__ void do_phase(
    unsigned char *dsm, uint32_t sb,
    const __half *__restrict__ xsrc, const __half *__restrict__ hprev,
    const float *__restrict__ bias,
    __half *__restrict__ dst, int row0, int col0, bool pre)
{
    const int tid = threadIdx.x, lane = tid & 31, wid = tid >> 5;
    const int wm = wid & 3, wn = wid >> 2;
    const int *toks = (const int *)(dsm + TOKS);

    float acc[2][4][4];
#pragma unroll
    for (int i = 0; i < 2; i++)
#pragma unroll
        for (int j = 0; j < 4; j++)
#pragma unroll
            for (int k = 0; k < 4; k++) acc[i][j][k] = 0.f;

    // lane-fixed fragment bases (proven b16 mapping)
    const uint32_t oA = (wm * 32 + (lane & 15)) * A_ROW + (lane >> 4) * 16;
    const uint32_t bB = sb + BOFF
                        + (wn * 32 + (lane & 7) + ((lane >> 4) << 3)) * B_ROW
                        + ((lane >> 3) & 1) * 16;

    if (!pre) {
        issueA<GATHER>(sb, toks, 0, xsrc, hprev, row0);
        issueA<GATHER>(sb, toks, 1, xsrc, hprev, row0);
    }

#pragma unroll 1
    for (int c = 0; c < 16; c++) {
        if (c < 15) asm volatile("cp.async.wait_group 1;" ::: "memory");
        else        asm volatile("cp.async.wait_group 0;" ::: "memory");
        __syncthreads();     // all warps done with buf (c-1)%3; buf c%3 visible
        if (c < 14) issueA<GATHER>(sb, toks, c + 2, xsrc, hprev, row0);

        const uint32_t abuf = sb + AOFF + (uint32_t)(c % 3) * ABUF + oA;
        const uint32_t bbuf = bB + c * 128;

        // register-double-buffered fragments: LDSM(ks+1) before MMA(ks)
        uint32_t fa[2][8], fb[2][8];
        LDSM4(&fa[0][0], abuf);
        LDSM4(&fa[0][4], abuf + 16 * A_ROW);
        LDSM4(&fb[0][0], bbuf);
        LDSM4(&fb[0][4], bbuf + 16 * B_ROW);
#pragma unroll
        for (int ks = 0; ks < 4; ks++) {
            const int cu = ks & 1;
            if (ks < 3) {
                const uint32_t aa = abuf + (ks + 1) * 32;
                const uint32_t ba = bbuf + (ks + 1) * 32;
                LDSM4(&fa[cu ^ 1][0], aa);
                LDSM4(&fa[cu ^ 1][4], aa + 16 * A_ROW);
                LDSM4(&fb[cu ^ 1][0], ba);
                LDSM4(&fb[cu ^ 1][4], ba + 16 * B_ROW);
            }
            mma_f16(acc[0][0], &fa[cu][0], fb[cu][0], fb[cu][1]);
            mma_f16(acc[0][1], &fa[cu][0], fb[cu][2], fb[cu][3]);
            mma_f16(acc[0][2], &fa[cu][0], fb[cu][4], fb[cu][5]);
            mma_f16(acc[0][3], &fa[cu][0], fb[cu][6], fb[cu][7]);
            mma_f16(acc[1][0], &fa[cu][4], fb[cu][0], fb[cu][1]);
            mma_f16(acc[1][1], &fa[cu][4], fb[cu][2], fb[cu][3]);
            mma_f16(acc[1][2], &fa[cu][4], fb[cu][4], fb[cu][5]);
            mma_f16(acc[1][3], &fa[cu][4], fb[cu][6], fb[cu][7]);
        }
    }

    // epilogue: bias + tanh -> fp16 h state
#pragma unroll
    for (int mt = 0; mt < 2; mt++) {
        const int mrow = row0 + wm * 32 + mt * 16 + (lane >> 2);
#pragma unroll
        for (int oct = 0; oct < 4; oct++) {
            const int ncol = col0 + wn * 32 + oct * 8 + 2 * (lane & 3);
            float bv0 = __ldg(bias + ncol), bv1 = __ldg(bias + ncol + 1);
            __half2 v0 = __floats2half2_rn(tanhf(acc[mt][oct][0] + bv0),
                                           tanhf(acc[mt][oct][1] + bv1));
            __half2 v1 = __floats2half2_rn(tanhf(acc[mt][oct][2] + bv0),
                                           tanhf(acc[mt][oct][3] + bv1));
            *(__half2 *)(dst + (size_t)mrow * U_SZ + ncol) = v0;
            *(__half2 *)(dst + (size_t)(mrow + 8) * U_SZ + ncol) = v1;
        }
    }
}

extern "C" __global__ void __launch_bounds__(NTHR, 1)
rnn_kernel(const int *__restrict__ tok32,
           const float *__restrict__ emb,
           const float *__restrict__ W0x, const float *__restrict__ W0h,
           const float *__restrict__ b0,
           const float *__restrict__ W1x, const float *__restrict__ W1h,
           const float *__restrict__ b1,
           const float *__restrict__ Wout, const float *__restrict__ bout,
           float *__restrict__ out)
{
    extern __shared__ __align__(128) unsigned char dsm[];
    const uint32_t sb = smem_u32(dsm);
    const int tid = threadIdx.x, wid = tid >> 5, lane = tid & 31;
    const int cta = blockIdx.x;
    const bool cell0 = (cta < 64);
    const int local = cell0 ? cta : cta - 64;
    const int row0 = (local >> 3) * 128;   // 8 row tiles of 128
    const int col0 = (local & 7) * 64;     // 8 col tiles of 64
    const int gtid = cta * NTHR + tid, gstride = NCTA * NTHR;
    int *toks = (int *)(dsm + TOKS);

    unsigned barBase = 0;
    if (tid == 0) barBase = *(volatile unsigned *)&g_gen;
    unsigned nb = 0;

    // token dtype autodetect (proven)
    __shared__ int s_stride;
    if (tid == 0) {
        bool hz = true;
#pragma unroll 1
        for (int i = 0; i < 32; i++)
            if (__ldg(tok32 + 2 * i + 1) != 0) { hz = false; break; }
        s_stride = hz ? 2 : 1;
    }
    __syncthreads();
    const int tokStride = s_stride;

    // ---- per-launch prep ----
    for (int i = gtid; i < VOCAB * U_SZ / 4; i += gstride) {
        float4 v = __ldg((const float4 *)emb + i);
        __half2 h0 = __floats2half2_rn(v.x, v.y);
        __half2 h1 = __floats2half2_rn(v.z, v.w);
        *(uint2 *)(g_X + (size_t)i * 4) =
            make_uint2(*(uint32_t *)&h0, *(uint32_t *)&h1);
    }
    for (int i = gtid; i < U_SZ * KTOT; i += gstride) {
        int n = i & 511, k = i >> 9;
        float v0 = (k < U_SZ) ? __ldg(W0x + (size_t)k * U_SZ + n)
                              : __ldg(W0h + (size_t)(k - U_SZ) * U_SZ + n);
        float v1 = (k < U_SZ) ? __ldg(W1x + (size_t)k * U_SZ + n)
                              : __ldg(W1h + (size_t)(k - U_SZ) * U_SZ + n);
        size_t o = (size_t)n * KTOT + k;
        g_B[0][o] = __float2half_rn(v0);
        g_B[1][o] = __float2half_rn(v1);
    }
    for (int i = gtid; i < B_SZ * U_SZ / 8; i += gstride) {
        ((uint4 *)g_H0[0])[i] = make_uint4(0, 0, 0, 0);
        ((uint4 *)g_H1[0])[i] = make_uint4(0, 0, 0, 0);
    }
    // toks for t=0 (cell0 only; input is const, no barrier needed)
    if (cell0 && tid < 128)
        toks[tid] = tok32[((size_t)(row0 + tid) * T_SZ + 0) * tokStride];
    grid_barrier(barBase, ++nb);

    // ---- stage this CTA's weight slice into resident smem (once) ----
    {
        const __half *bw = cell0 ? g_B[0] : g_B[1];
        for (int i = tid; i < 64 * 128; i += NTHR) {       // 64 rows x 128 uint4
            int n = i >> 7, q = i & 127;
            uint4 v = __ldcg((const uint4 *)(bw + (size_t)(col0 + n) * KTOT + q * 8));
            *(uint4 *)(dsm + BOFF + n * B_ROW + q * 16) = v;
        }
    }
    // (visibility of B before first LDSM is covered by the in-phase syncthreads)

    // ---- pipelined recurrence: 81 periods ----
    // cell0 at period p computes t=p; cell1 computes t=p-1.
    // h(t) written to buf[(t&1)^1]; h(t-1) read from buf[t&1].
    for (int p = 0; p <= T_SZ; p++) {
        if (cell0) {
            if (p <= T_SZ - 1) {
                int t = p, rb = t & 1;
                do_phase<true>(dsm, sb, g_X, g_H0[rb], b0,
                               g_H0[rb ^ 1], row0, col0, /*pre=*/p > 0);
                if (p < T_SZ - 1) {
                    // pre-barrier prefetch for phase t+1: toks + emb chunks 0,1
                    __syncthreads();            // all warps done with A bufs/toks
                    if (tid < 128)
                        toks[tid] = tok32[((size_t)(row0 + tid) * T_SZ + (t + 1))
                                          * tokStride];
                    __syncthreads();            // toks visible to all issuers
                    issueA<true>(sb, toks, 0, g_X, nullptr, row0);
                    issueA<true>(sb, toks, 1, g_X, nullptr, row0);
                }
            }
        } else {
            if (p >= 1) {
                int t = p - 1, rb = t & 1;
                do_phase<false>(dsm, sb,
                                g_H0[rb ^ 1],      // x = h0(t)
                                g_H1[rb],          // h1(t-1)
                                b1, g_H1[rb ^ 1], row0, col0, /*pre=*/false);
            }
        }
        grid_barrier(barBase, ++nb);
    }

    // ---- final dense + sigmoid: h1(79) in buffer 0; L1-bypass reads ----
    {
        int b = cta * 8 + wid;               // 1024 rows
        const __half *fh = g_H1[0];
        float s = 0.f;
#pragma unroll
        for (int j = 0; j < 8; j++) {
            int k = lane * 2 + 64 * j;
            uint32_t u = __ldcg((const uint32_t *)(fh + (size_t)b * U_SZ + k));
            __half2 v = *reinterpret_cast<__half2 *>(&u);
            s += __half2float(v.x) * __ldg(Wout + k);
            s += __half2float(v.y) * __ldg(Wout + k + 1);
        }
#pragma unroll
        for (int off = 16; off; off >>= 1)
            s += __shfl_down_sync(0xffffffffu, s, off);
        if (lane == 0) {
            float z = s + __ldg(bout);
            out[b] = 1.f / (1.f + expf(-z));
        }
    }
}

extern "C" void kernel_launch(void *const *d_in, const int *in_sizes, int n_in,
                              void *d_out, int out_size)
{
    const int   *inputs = (const int *)d_in[0];
    const float *emb  = (const float *)d_in[1];
    const float *W0x  = (const float *)d_in[2];
    const float *W0h  = (const float *)d_in[3];
    const float *b0   = (const float *)d_in[4];
    const float *W1x  = (const float *)d_in[5];
    const float *W1h  = (const float *)d_in[6];
    const float *b1   = (const float *)d_in[7];
    const float *Wout = (const float *)d_in[8];
    const float *bout = (const float *)d_in[9];
    cudaFuncSetAttribute(rnn_kernel, cudaFuncAttributeMaxDynamicSharedMemorySize,
                         SM_TOTAL);
    rnn_kernel<<<NCTA, NTHR, SM_TOTAL>>>(inputs, emb, W0x, W0h, b0,
                                         W1x, W1h, b1, Wout, bout,
                                         (float *)d_out);
}

// round 17
// speedup vs baseline: 18.0408x; 1.2858x over previous
#include <cuda_runtime.h>
#include <cuda_fp16.h>
#include <cstdint>

// ============================================================================
// 2-layer SimpleRNN, mma.sync fp16 single-pass (f32 accum).
// R17: warp-autonomous phases. Warp tile 16(batch) x 64(units): each warp
// stages ITS OWN 16 A-rows via cp.async, waits its own groups, LDSMs its own
// rows; B resident in smem (read-only) -> ZERO __syncthreads inside a phase.
// Tokens live in 4 regs/lane. Cell0 pre-issues 3 emb chunks pre-barrier.
// Split-grid pipeline (cell0: CTAs 0-63, cell1: 64-127) -> 81 periods.
// ============================================================================

#define NCTA  128
#define NTHR  256
#define B_SZ  1024
#define T_SZ  80
#define U_SZ  512
#define KTOT  1024
#define VOCAB 50000

// smem layout
#define B_ROW 2064                       // 1024 fp16 + 16B pad (129*16 units)
#define BOFF  0                          // B: 64 rows x 2064 = 132096
#define AOFF  132096
#define A_ROW 144                        // 64 fp16 + 16B pad (9*16 units)
#define ABUF  (128 * A_ROW)              // 18432 per buffer, x3
#define SM_TOTAL (AOFF + 3 * ABUF + 256) // 187648

// ---- global scratch ----
__device__ __half g_X[VOCAB * U_SZ];
__device__ __half g_B[2][U_SZ * KTOT];            // [cell][n*1024+k] = Wcat[k][n]
__device__ __half g_H0[2][B_SZ * U_SZ];
__device__ __half g_H1[2][B_SZ * U_SZ];
__device__ unsigned g_arrive = 0, g_gen = 0;

__device__ __forceinline__ uint32_t smem_u32(const void *p) {
    uint32_t a;
    asm("{ .reg .u64 t; cvta.to.shared.u64 t, %1; cvt.u32.u64 %0, t; }"
        : "=r"(a) : "l"(p));
    return a;
}
#define LDSM4(r, a) \
    asm volatile("ldmatrix.sync.aligned.m8n8.x4.shared.b16 {%0,%1,%2,%3}, [%4];" \
        : "=r"((r)[0]), "=r"((r)[1]), "=r"((r)[2]), "=r"((r)[3]) : "r"(a))

__device__ __forceinline__ void mma_f16(float *d, const uint32_t *a,
                                        uint32_t b0, uint32_t b1) {
    asm volatile(
        "mma.sync.aligned.m16n8k16.row.col.f32.f16.f16.f32 "
        "{%0,%1,%2,%3}, {%4,%5,%6,%7}, {%8,%9}, {%0,%1,%2,%3};"
        : "+f"(d[0]), "+f"(d[1]), "+f"(d[2]), "+f"(d[3])
        : "r"(a[0]), "r"(a[1]), "r"(a[2]), "r"(a[3]), "r"(b0), "r"(b1));
}
__device__ __forceinline__ void cpa16(uint32_t s, const void *g) {
    asm volatile("cp.async.cg.shared.global [%0], [%1], 16;" :: "r"(s), "l"(g));
}
#define CPA_COMMIT() asm volatile("cp.async.commit_group;" ::: "memory")

__device__ __forceinline__ void grid_barrier(unsigned barBase, unsigned n) {
    __syncthreads();
    if (threadIdx.x == 0) {
        __threadfence();
        unsigned rank = atomicAdd(&g_arrive, 1);
        if (rank == NCTA - 1) {
            g_arrive = 0;
            __threadfence();
            atomicAdd(&g_gen, 1);
        } else {
            unsigned target = barBase + n;
            while ((int)(*(volatile unsigned *)&g_gen - target) < 0) { }
            __threadfence();
        }
    }
    __syncthreads();
}

// per-warp: stage one K=64 chunk of THIS WARP's 16 A rows (chunks 0-7: x part,
// 8-15: h part). lane covers rows 4i+(lane>>3), col-quad lane&7.
template <bool GATHER>
__device__ __forceinline__ void issueA(
    uint32_t sb, int wid, int lane, const int *tokr, int c,
    const __half *__restrict__ xsrc, const __half *__restrict__ hprev, int row0)
{
    const uint32_t bufb = sb + AOFF + (uint32_t)(c % 3) * ABUF;
    const int kb = c * 64;
    const bool xp = (kb < U_SZ);
    const int kk = xp ? kb : kb - U_SZ;
    const __half *src = xp ? xsrc : hprev;
    const int q = lane & 7;
#pragma unroll
    for (int i = 0; i < 4; i++) {
        int r = 4 * i + (lane >> 3);              // 0..15 (warp-local row)
        size_t go = (GATHER && xp)
                        ? (size_t)tokr[i] * U_SZ + kk + q * 8
                        : (size_t)(row0 + wid * 16 + r) * U_SZ + kk + q * 8;
        cpa16(bufb + (wid * 16 + r) * A_ROW + q * 16, src + go);
    }
    CPA_COMMIT();
}

// ---- one GEMM phase: warp computes 16x64 of tanh([x|h]@Wcat + bias) ----
template <bool GATHER>
__device__ __forceinline__ void do_phase(
    uint32_t sb, int wid, int lane, const int *tokr,
    const __half *__restrict__ xsrc, const __half *__restrict__ hprev,
    const float *__restrict__ bias,
    __half *__restrict__ dst, int row0, int col0, bool pre)
{
    float acc[8][4];
#pragma unroll
    for (int o = 0; o < 8; o++)
#pragma unroll
        for (int j = 0; j < 4; j++) acc[o][j] = 0.f;

    // lane-fixed fragment bases (proven b16 mappings)
    const uint32_t oA = (wid * 16 + (lane & 15)) * A_ROW + (lane >> 4) * 16;
    const uint32_t bB = sb + BOFF
                        + ((lane & 7) + ((lane >> 4) << 3)) * B_ROW
                        + ((lane >> 3) & 1) * 16;

    if (!pre) {
        issueA<GATHER>(sb, wid, lane, tokr, 0, xsrc, hprev, row0);
        issueA<GATHER>(sb, wid, lane, tokr, 1, xsrc, hprev, row0);
        issueA<GATHER>(sb, wid, lane, tokr, 2, xsrc, hprev, row0);
    }

#pragma unroll 1
    for (int c = 0; c < 16; c++) {
        // per-warp wait: groups retire in order; ensure group c landed
        if (c < 14)       asm volatile("cp.async.wait_group 2;" ::: "memory");
        else if (c == 14) asm volatile("cp.async.wait_group 1;" ::: "memory");
        else              asm volatile("cp.async.wait_group 0;" ::: "memory");

        const uint32_t abuf = sb + AOFF + (uint32_t)(c % 3) * ABUF + oA;
        const uint32_t bbuf = bB + c * 128;

        uint32_t fa[2][4], fb[2][16];
        LDSM4(fa[0], abuf);
#pragma unroll
        for (int j = 0; j < 4; j++) LDSM4(&fb[0][4 * j], bbuf + j * 16 * B_ROW);
#pragma unroll
        for (int ks = 0; ks < 4; ks++) {
            const int cu = ks & 1;
            if (ks < 3) {
                LDSM4(fa[cu ^ 1], abuf + (ks + 1) * 32);
#pragma unroll
                for (int j = 0; j < 4; j++)
                    LDSM4(&fb[cu ^ 1][4 * j],
                          bbuf + j * 16 * B_ROW + (ks + 1) * 32);
            }
#pragma unroll
            for (int o = 0; o < 8; o++)
                mma_f16(acc[o], fa[cu], fb[cu][2 * o], fb[cu][2 * o + 1]);
        }
        // refill buffer (c%3) for chunk c+3: warp's own LDSMs for chunk c are
        // complete (MMAs above issued), so the overwrite is safe. No syncs.
        if (c < 13)
            issueA<GATHER>(sb, wid, lane, tokr, c + 3, xsrc, hprev, row0);
    }

    // epilogue: bias + tanh -> fp16 h state (warp-exclusive rows)
    const int mrow = row0 + wid * 16 + (lane >> 2);
#pragma unroll
    for (int o = 0; o < 8; o++) {
        const int ncol = col0 + o * 8 + 2 * (lane & 3);
        float bv0 = __ldg(bias + ncol), bv1 = __ldg(bias + ncol + 1);
        __half2 v0 = __floats2half2_rn(tanhf(acc[o][0] + bv0),
                                       tanhf(acc[o][1] + bv1));
        __half2 v1 = __floats2half2_rn(tanhf(acc[o][2] + bv0),
                                       tanhf(acc[o][3] + bv1));
        *(__half2 *)(dst + (size_t)mrow * U_SZ + ncol) = v0;
        *(__half2 *)(dst + (size_t)(mrow + 8) * U_SZ + ncol) = v1;
    }
}

extern "C" __global__ void __launch_bounds__(NTHR, 1)
rnn_kernel(const int *__restrict__ tok32,
           const float *__restrict__ emb,
           const float *__restrict__ W0x, const float *__restrict__ W0h,
           const float *__restrict__ b0,
           const float *__restrict__ W1x, const float *__restrict__ W1h,
           const float *__restrict__ b1,
           const float *__restrict__ Wout, const float *__restrict__ bout,
           float *__restrict__ out)
{
    extern __shared__ __align__(128) unsigned char dsm[];
    const uint32_t sb = smem_u32(dsm);
    const int tid = threadIdx.x, wid = tid >> 5, lane = tid & 31;
    const int cta = blockIdx.x;
    const bool cell0 = (cta < 64);
    const int local = cell0 ? cta : cta - 64;
    const int row0 = (local >> 3) * 128;   // 8 row tiles of 128
    const int col0 = (local & 7) * 64;     // 8 col tiles of 64
    const int gtid = cta * NTHR + tid, gstride = NCTA * NTHR;

    unsigned barBase = 0;
    if (tid == 0) barBase = *(volatile unsigned *)&g_gen;
    unsigned nb = 0;

    // token dtype autodetect (proven)
    __shared__ int s_stride;
    if (tid == 0) {
        bool hz = true;
#pragma unroll 1
        for (int i = 0; i < 32; i++)
            if (__ldg(tok32 + 2 * i + 1) != 0) { hz = false; break; }
        s_stride = hz ? 2 : 1;
    }
    __syncthreads();
    const int tokStride = s_stride;

    // ---- per-launch prep ----
    for (int i = gtid; i < VOCAB * U_SZ / 4; i += gstride) {
        float4 v = __ldg((const float4 *)emb + i);
        __half2 h0 = __floats2half2_rn(v.x, v.y);
        __half2 h1 = __floats2half2_rn(v.z, v.w);
        *(uint2 *)(g_X + (size_t)i * 4) =
            make_uint2(*(uint32_t *)&h0, *(uint32_t *)&h1);
    }
    for (int i = gtid; i < U_SZ * KTOT; i += gstride) {
        int n = i & 511, k = i >> 9;
        float v0 = (k < U_SZ) ? __ldg(W0x + (size_t)k * U_SZ + n)
                              : __ldg(W0h + (size_t)(k - U_SZ) * U_SZ + n);
        float v1 = (k < U_SZ) ? __ldg(W1x + (size_t)k * U_SZ + n)
                              : __ldg(W1h + (size_t)(k - U_SZ) * U_SZ + n);
        size_t o = (size_t)n * KTOT + k;
        g_B[0][o] = __float2half_rn(v0);
        g_B[1][o] = __float2half_rn(v1);
    }
    for (int i = gtid; i < B_SZ * U_SZ / 8; i += gstride) {
        ((uint4 *)g_H0[0])[i] = make_uint4(0, 0, 0, 0);
        ((uint4 *)g_H1[0])[i] = make_uint4(0, 0, 0, 0);
    }
    grid_barrier(barBase, ++nb);

    // ---- stage this CTA's weight slice into resident smem (once) ----
    {
        const __half *bw = cell0 ? g_B[0] : g_B[1];
        for (int i = tid; i < 64 * 128; i += NTHR) {       // 64 rows x 128 uint4
            int n = i >> 7, q = i & 127;
            uint4 v = __ldcg((const uint4 *)(bw + (size_t)(col0 + n) * KTOT + q * 8));
            *(uint4 *)(dsm + BOFF + n * B_ROW + q * 16) = v;
        }
    }
    __syncthreads();   // B visible to all warps before any phase

    // per-lane token regs (rows 4i+(lane>>3) of this warp's 16-row slice)
    int tokr[4] = {0, 0, 0, 0};
    auto load_toks = [&](int t) {
#pragma unroll
        for (int i = 0; i < 4; i++) {
            int r = row0 + wid * 16 + 4 * i + (lane >> 3);
            tokr[i] = __ldg(tok32 + ((size_t)r * T_SZ + t) * tokStride);
        }
    };
    if (cell0) load_toks(0);

    // ---- pipelined recurrence: 81 periods ----
    // cell0 at period p computes t=p; cell1 computes t=p-1.
    // h(t) written to buf[(t&1)^1]; h(t-1) read from buf[t&1].
    for (int p = 0; p <= T_SZ; p++) {
        if (cell0) {
            if (p <= T_SZ - 1) {
                int t = p, rb = t & 1;
                do_phase<true>(sb, wid, lane, tokr, g_X, g_H0[rb], b0,
                               g_H0[rb ^ 1], row0, col0, /*pre=*/p > 0);
                if (p < T_SZ - 1) {
                    // pre-barrier prefetch for t+1: tokens + 3 emb chunks
                    load_toks(t + 1);
                    issueA<true>(sb, wid, lane, tokr, 0, g_X, nullptr, row0);
                    issueA<true>(sb, wid, lane, tokr, 1, g_X, nullptr, row0);
                    issueA<true>(sb, wid, lane, tokr, 2, g_X, nullptr, row0);
                }
            }
        } else {
            if (p >= 1) {
                int t = p - 1, rb = t & 1;
                do_phase<false>(sb, wid, lane, tokr,
                                g_H0[rb ^ 1],      // x = h0(t)
                                g_H1[rb],          // h1(t-1)
                                b1, g_H1[rb ^ 1], row0, col0, /*pre=*/false);
            }
        }
        grid_barrier(barBase, ++nb);
    }

    // ---- final dense + sigmoid: h1(79) in buffer 0; L1-bypass reads ----
    {
        int b = cta * 8 + wid;               // 1024 rows
        const __half *fh = g_H1[0];
        float s = 0.f;
#pragma unroll
        for (int j = 0; j < 8; j++) {
            int k = lane * 2 + 64 * j;
            uint32_t u = __ldcg((const uint32_t *)(fh + (size_t)b * U_SZ + k));
            __half2 v = *reinterpret_cast<__half2 *>(&u);
            s += __half2float(v.x) * __ldg(Wout + k);
            s += __half2float(v.y) * __ldg(Wout + k + 1);
        }
#pragma unroll
        for (int off = 16; off; off >>= 1)
            s += __shfl_down_sync(0xffffffffu, s, off);
        if (lane == 0) {
            float z = s + __ldg(bout);
            out[b] = 1.f / (1.f + expf(-z));
        }
    }
}

extern "C" void kernel_launch(void *const *d_in, const int *in_sizes, int n_in,
                              void *d_out, int out_size)
{
    const int   *inputs = (const int *)d_in[0];
    const float *emb  = (const float *)d_in[1];
    const float *W0x  = (const float *)d_in[2];
    const float *W0h  = (const float *)d_in[3];
    const float *b0   = (const float *)d_in[4];
    const float *W1x  = (const float *)d_in[5];
    const float *W1h  = (const float *)d_in[6];
    const float *b1   = (const float *)d_in[7];
    const float *Wout = (const float *)d_in[8];
    const float *bout = (const float *)d_in[9];
    cudaFuncSetAttribute(rnn_kernel, cudaFuncAttributeMaxDynamicSharedMemorySize,
                         SM_TOTAL);
    rnn_kernel<<<NCTA, NTHR, SM_TOTAL>>>(inputs, emb, W0x, W0h, b0,
                                         W1x, W1h, b1, Wout, bout,
                                         (float *)d_out);
}